// round 5
// baseline (speedup 1.0000x reference)
#include <cuda_runtime.h>
#include <cstdint>

// out[p] = (L >= 0) || (missing(p) - L >= 0.5), written as float 0.0/1.0
// L = 7-point Laplacian (6*center - face neighbors, zero padding);
// missing(p) = # out-of-grid face neighbors (kernel sums to 0 =>
// conv(1-m,k) = missing(p) - conv(m,k)).
//
// 8-wide x per thread (two float4), rolling A/B planes over KZ z-slices.
// 6x LDG.128 + 2x LDG.32 per iteration per thread -> high per-warp MLP.
// Streaming stores (__stcs) keep the write-once output out of L2.

#define DSZ 192
#define KZ  6
#define ZT  (DSZ / KZ)   // 32 z-tiles

__global__ __launch_bounds__(384, 3) void mask_kernel(
    const float* __restrict__ m, float* __restrict__ out)
{
    const int tx = threadIdx.x;                       // 0..23 -> x octet
    const int y  = blockIdx.y * blockDim.y + threadIdx.y;
    const int zb = blockIdx.z;
    const int z0 = (zb & (ZT - 1)) * KZ;
    const int b  = zb / ZT;
    const int x0 = tx * 8;

    const size_t plane = (size_t)DSZ * DSZ;
    const float* p = m + (((size_t)b * DSZ + z0) * DSZ + y) * DSZ + x0;
    float* q = out + (((size_t)b * DSZ + z0) * DSZ + y) * DSZ + x0;

    const float4 zero4 = make_float4(0.f, 0.f, 0.f, 0.f);
    const bool hasYm = (y > 0);
    const bool hasYp = (y < DSZ - 1);
    const bool hasXl = (x0 > 0);
    const bool hasXr = (x0 + 8 < DSZ);
    const float missY = (float)((int)(!hasYm) + (int)(!hasYp));

    float4 A0 = (z0 > 0) ? *(const float4*)(p - plane)     : zero4;
    float4 A1 = (z0 > 0) ? *(const float4*)(p - plane + 4) : zero4;
    float4 B0 = *(const float4*)(p);
    float4 B1 = *(const float4*)(p + 4);

    #pragma unroll
    for (int iz = 0; iz < KZ; ++iz) {
        const int z = z0 + iz;
        const bool hasZp = (z < DSZ - 1);
        float4 C0  = hasZp  ? *(const float4*)(p + plane)     : zero4;
        float4 C1  = hasZp  ? *(const float4*)(p + plane + 4) : zero4;
        float4 ym0 = hasYm ? *(const float4*)(p - DSZ)        : zero4;
        float4 ym1 = hasYm ? *(const float4*)(p - DSZ + 4)    : zero4;
        float4 yp0 = hasYp ? *(const float4*)(p + DSZ)        : zero4;
        float4 yp1 = hasYp ? *(const float4*)(p + DSZ + 4)    : zero4;
        float  xl  = hasXl ? __ldg(p - 1) : 0.f;
        float  xr  = hasXr ? __ldg(p + 8) : 0.f;

        float L0 = 6.f * B0.x - (xl   + B0.y + ym0.x + yp0.x + A0.x + C0.x);
        float L1 = 6.f * B0.y - (B0.x + B0.z + ym0.y + yp0.y + A0.y + C0.y);
        float L2 = 6.f * B0.z - (B0.y + B0.w + ym0.z + yp0.z + A0.z + C0.z);
        float L3 = 6.f * B0.w - (B0.z + B1.x + ym0.w + yp0.w + A0.w + C0.w);
        float L4 = 6.f * B1.x - (B0.w + B1.y + ym1.x + yp1.x + A1.x + C1.x);
        float L5 = 6.f * B1.y - (B1.x + B1.z + ym1.y + yp1.y + A1.y + C1.y);
        float L6 = 6.f * B1.z - (B1.y + B1.w + ym1.z + yp1.z + A1.z + C1.z);
        float L7 = 6.f * B1.w - (B1.z + xr   + ym1.w + yp1.w + A1.w + C1.w);

        const float mz = missY + (float)((int)(z == 0) + (int)(z == DSZ - 1));
        const float f0 = mz + (float)(int)(!hasXl);
        const float f7 = mz + (float)(int)(!hasXr);

        float4 o0, o1;
        o0.x = ((L0 >= 0.f) || (f0 - L0 >= 0.5f)) ? 1.f : 0.f;
        o0.y = ((L1 >= 0.f) || (mz - L1 >= 0.5f)) ? 1.f : 0.f;
        o0.z = ((L2 >= 0.f) || (mz - L2 >= 0.5f)) ? 1.f : 0.f;
        o0.w = ((L3 >= 0.f) || (mz - L3 >= 0.5f)) ? 1.f : 0.f;
        o1.x = ((L4 >= 0.f) || (mz - L4 >= 0.5f)) ? 1.f : 0.f;
        o1.y = ((L5 >= 0.f) || (mz - L5 >= 0.5f)) ? 1.f : 0.f;
        o1.z = ((L6 >= 0.f) || (mz - L6 >= 0.5f)) ? 1.f : 0.f;
        o1.w = ((L7 >= 0.f) || (f7 - L7 >= 0.5f)) ? 1.f : 0.f;

        __stcs((float4*)q, o0);
        __stcs((float4*)(q + 4), o1);

        A0 = B0; A1 = B1; B0 = C0; B1 = C1;
        p += plane; q += plane;
    }
}

extern "C" void kernel_launch(void* const* d_in, const int* in_sizes, int n_in,
                              void* d_out, int out_size)
{
    const float* m = (const float*)d_in[0];
    float* out = (float*)d_out;

    dim3 block(24, 16, 1);                // 384 threads: full 192-wide row x 16 rows
    dim3 grid(1, DSZ / 16, 2 * ZT);       // y-tiles, (batch * z-tiles)
    mask_kernel<<<grid, block>>>(m, out);
}

// round 6
// speedup vs baseline: 1.0793x; 1.0793x over previous
#include <cuda_runtime.h>
#include <cstdint>

// out[p] = (L >= 0) || (missing(p) - L >= 0.5), float 0.0/1.0
// L = 7-point Laplacian (6*center - face neighbors, zero padding);
// missing(p) = # out-of-grid face neighbors (kernel sums to 0 =>
// conv(1-m,k) = missing(p) - conv(m,k)).
//
// Pair-z kernel: one thread computes an x-quad at z and z+1.
// 8 independent float4 loads + 4 scalars, no loop, no rolling registers:
// ptxas can batch everything -> max in-flight bytes per warp.

#define DSZ 192

__global__ __launch_bounds__(384) void mask_kernel(
    const float* __restrict__ m, float* __restrict__ out)
{
    const int tx = threadIdx.x;                        // 0..47 -> x quad
    const int y  = blockIdx.y * blockDim.y + threadIdx.y;
    const int zb = blockIdx.z;                         // 0..191: b*96 + zpair
    const int zp = zb % 96;
    const int b  = zb / 96;
    const int z  = zp * 2;                             // 0..190
    const int x0 = tx * 4;

    const size_t plane = (size_t)DSZ * DSZ;
    const float* p = m + (((size_t)b * DSZ + z) * DSZ + y) * DSZ + x0;
    float* q = out + (((size_t)b * DSZ + z) * DSZ + y) * DSZ + x0;

    const float4 zero4 = make_float4(0.f, 0.f, 0.f, 0.f);
    const bool hasYm = (y > 0);
    const bool hasYp = (y < DSZ - 1);
    const bool hasXl = (x0 > 0);
    const bool hasXr = (x0 + 4 < DSZ);

    // ---- all loads independent: issue as one batch ----
    float4 P0  = (z > 0)        ? *(const float4*)(p - plane)        : zero4; // z-1
    float4 P1  = *(const float4*)(p);                                          // z
    float4 P2  = *(const float4*)(p + plane);                                  // z+1
    float4 P3  = (z + 2 < DSZ)  ? *(const float4*)(p + 2 * plane)    : zero4; // z+2
    float4 ym1 = hasYm ? *(const float4*)(p - DSZ)          : zero4;
    float4 yp1 = hasYp ? *(const float4*)(p + DSZ)          : zero4;
    float4 ym2 = hasYm ? *(const float4*)(p + plane - DSZ)  : zero4;
    float4 yp2 = hasYp ? *(const float4*)(p + plane + DSZ)  : zero4;
    float  xl1 = hasXl ? __ldg(p - 1)         : 0.f;
    float  xr1 = hasXr ? __ldg(p + 4)         : 0.f;
    float  xl2 = hasXl ? __ldg(p + plane - 1) : 0.f;
    float  xr2 = hasXr ? __ldg(p + plane + 4) : 0.f;

    const float missY = (float)((int)(!hasYm) + (int)(!hasYp));
    const float mA = missY + (float)(int)(z == 0);        // slice z (z+1 in-grid)
    const float mB = missY + (float)(int)(z + 2 == DSZ);  // slice z+1 (z in-grid)
    const float eL = (float)(int)(!hasXl);
    const float eR = (float)(int)(!hasXr);

    // ---- slice z ----
    {
        float L0 = 6.f * P1.x - (xl1  + P1.y + ym1.x + yp1.x + P0.x + P2.x);
        float L1 = 6.f * P1.y - (P1.x + P1.z + ym1.y + yp1.y + P0.y + P2.y);
        float L2 = 6.f * P1.z - (P1.y + P1.w + ym1.z + yp1.z + P0.z + P2.z);
        float L3 = 6.f * P1.w - (P1.z + xr1  + ym1.w + yp1.w + P0.w + P2.w);
        float4 o;
        o.x = ((L0 >= 0.f) || (mA + eL - L0 >= 0.5f)) ? 1.f : 0.f;
        o.y = ((L1 >= 0.f) || (mA      - L1 >= 0.5f)) ? 1.f : 0.f;
        o.z = ((L2 >= 0.f) || (mA      - L2 >= 0.5f)) ? 1.f : 0.f;
        o.w = ((L3 >= 0.f) || (mA + eR - L3 >= 0.5f)) ? 1.f : 0.f;
        *(float4*)(q) = o;
    }

    // ---- slice z+1 ----
    {
        float L0 = 6.f * P2.x - (xl2  + P2.y + ym2.x + yp2.x + P1.x + P3.x);
        float L1 = 6.f * P2.y - (P2.x + P2.z + ym2.y + yp2.y + P1.y + P3.y);
        float L2 = 6.f * P2.z - (P2.y + P2.w + ym2.z + yp2.z + P1.z + P3.z);
        float L3 = 6.f * P2.w - (P2.z + xr2  + ym2.w + yp2.w + P1.w + P3.w);
        float4 o;
        o.x = ((L0 >= 0.f) || (mB + eL - L0 >= 0.5f)) ? 1.f : 0.f;
        o.y = ((L1 >= 0.f) || (mB      - L1 >= 0.5f)) ? 1.f : 0.f;
        o.z = ((L2 >= 0.f) || (mB      - L2 >= 0.5f)) ? 1.f : 0.f;
        o.w = ((L3 >= 0.f) || (mB + eR - L3 >= 0.5f)) ? 1.f : 0.f;
        *(float4*)(q + plane) = o;
    }
}

extern "C" void kernel_launch(void* const* d_in, const int* in_sizes, int n_in,
                              void* d_out, int out_size)
{
    const float* m = (const float*)d_in[0];
    float* out = (float*)d_out;

    dim3 block(48, 8, 1);                 // 384 threads: full row x 8 rows
    dim3 grid(1, DSZ / 8, 2 * (DSZ / 2)); // y-tiles, (batch * z-pairs)
    mask_kernel<<<grid, block>>>(m, out);
}